// round 3
// baseline (speedup 1.0000x reference)
#include <cuda_runtime.h>

#define SDIM 56
#define NCELL 3136
#define NITEM 6272
#define NCLS 20
#define IMG_STRIDE 94080
#define CONF_OFF 62720
#define COORD_OFF 68992
#define MAXOUT 30
#define NCAND 256
#define KEYBUF 2048
#define BATCH 256

__device__ float g_scores[BATCH * NITEM];
__device__ unsigned char g_cls[BATCH * NITEM];

// ---------------------------------------------------------------------------
// Kernel 1: decode scores + argmax class for every (cell, box). One thread/cell.
// ---------------------------------------------------------------------------
__global__ __launch_bounds__(256) void decode_kernel(const float* __restrict__ in)
{
    int gcell = blockIdx.x * 256 + threadIdx.x;
    if (gcell >= BATCH * NCELL) return;
    int img  = gcell / NCELL;
    int cell = gcell - img * NCELL;

    const float* base = in + (long)img * IMG_STRIDE;
    const float4* cp = (const float4*)(base + cell * NCLS);
    float p[NCLS];
    #pragma unroll
    for (int k = 0; k < 5; ++k) {
        float4 v = cp[k];
        p[4*k+0] = v.x; p[4*k+1] = v.y; p[4*k+2] = v.z; p[4*k+3] = v.w;
    }
    const float2 cf = *(const float2*)(base + CONF_OFF + cell * 2);
    float b0 = -1.0f, b1 = -1.0f;
    int a0 = 0, a1 = 0;
    #pragma unroll
    for (int c = 0; c < NCLS; ++c) {
        float v0 = cf.x * p[c];
        float v1 = cf.y * p[c];
        if (v0 > b0) { b0 = v0; a0 = c; }
        if (v1 > b1) { b1 = v1; a1 = c; }
    }
    float s0 = (b0 >= 0.1f) ? b0 : 0.0f;
    float s1 = (b1 >= 0.1f) ? b1 : 0.0f;
    long o = (long)img * NITEM + cell * 2;
    *(float2*)(g_scores + o) = make_float2(s0, s1);
    g_cls[o + 0] = (unsigned char)a0;
    g_cls[o + 1] = (unsigned char)a1;
}

// ---------------------------------------------------------------------------
// Kernel 2: per-image top-256 selection + greedy NMS. One block per image.
// ---------------------------------------------------------------------------
__global__ __launch_bounds__(256, 2) void nms_kernel(const float* __restrict__ in,
                                                     float* __restrict__ out)
{
    __shared__ float sc[NITEM];                              // scores; overlaid by SoA later
    __shared__ __align__(16) unsigned long long keys[KEYBUF]; // overlays 1024-bin histogram
    __shared__ int wsum[8];
    __shared__ int picks[MAXOUT];
    __shared__ int s_binsel;
    __shared__ int s_cnt;

    const int img = blockIdx.x;
    const int t = threadIdx.x;
    const int lane = t & 31;
    const int warp = t >> 5;
    const float* coord = in + (long)img * IMG_STRIDE + COORD_OFF;
    const float* gs = g_scores + (long)img * NITEM;
    const unsigned char* gc = g_cls + (long)img * NITEM;

    // ---- load scores into smem ----
    for (int i = t; i < NITEM / 4; i += 256)
        ((float4*)sc)[i] = ((const float4*)gs)[i];

    // ---- Phase B: 1024-bin histogram ----
    int* hist = (int*)keys;
    for (int k = t; k < 1024; k += 256) hist[k] = 0;
    if (t == 0) { s_binsel = 0; s_cnt = 0; }
    __syncthreads();
    for (int i = t; i < NITEM; i += 256) {
        int b = (int)(sc[i] * 1024.0f);
        b = b < 0 ? 0 : (b > 1023 ? 1023 : b);
        atomicAdd(&hist[b], 1);
    }
    __syncthreads();

    // ---- parallel suffix scan over 1024 bins -> largest b with suffix >= 256 ----
    {
        int4 h = ((const int4*)hist)[t];              // bins 4t .. 4t+3
        int v = h.x + h.y + h.z + h.w;
        #pragma unroll
        for (int off = 1; off < 32; off <<= 1) {
            int o = __shfl_down_sync(0xFFFFFFFFu, v, off);
            if (lane + off < 32) v += o;
        }
        if (lane == 0) wsum[warp] = v;                // warp total (lane0 holds full warp sum)
        __syncthreads();
        int tail = 0;
        #pragma unroll
        for (int w2 = 0; w2 < 8; ++w2) if (w2 > warp) tail += wsum[w2];
        int ssum = v + tail;                          // suffix over thread chunks from t..255
        int sfx0 = ssum;                              // suffix at bin 4t
        int sfx1 = sfx0 - h.x;
        int sfx2 = sfx1 - h.y;
        int sfx3 = sfx2 - h.z;
        int best = -1;
        if      (sfx3 >= NCAND) best = 4*t + 3;
        else if (sfx2 >= NCAND) best = 4*t + 2;
        else if (sfx1 >= NCAND) best = 4*t + 1;
        else if (sfx0 >= NCAND) best = 4*t;
        if (best >= 0) atomicMax(&s_binsel, best);
    }
    __syncthreads();
    const int bstar = s_binsel;

    // ---- Phase C: gather survivor keys (hist region dead) ----
    for (int i = t; i < NITEM; i += 256) {
        float s = sc[i];
        int b = (int)(s * 1024.0f);
        b = b < 0 ? 0 : (b > 1023 ? 1023 : b);
        if (b >= bstar) {
            int pos = atomicAdd(&s_cnt, 1);
            if (pos < KEYBUF) {
                unsigned long long key =
                    ((unsigned long long)__float_as_uint(s) << 13) |
                    (unsigned long long)(8191 - i);
                keys[pos] = key;
            }
        }
    }
    __syncthreads();
    int n = s_cnt; if (n > KEYBUF) n = KEYBUF;
    int np = NCAND; while (np < n) np <<= 1;
    for (int i = n + t; i < np; i += 256) keys[i] = 0ull;
    __syncthreads();

    // ---- Phase D: bitonic sort descending ----
    for (int k = 2; k <= np; k <<= 1) {
        for (int j = k >> 1; j > 0; j >>= 1) {
            for (int i = t; i < np; i += 256) {
                int ixj = i ^ j;
                if (ixj > i) {
                    unsigned long long a = keys[i];
                    unsigned long long b2 = keys[ixj];
                    bool up = ((i & k) == 0);
                    bool doswap = up ? (a < b2) : (a > b2);
                    if (doswap) { keys[i] = b2; keys[ixj] = a; }
                }
            }
            __syncthreads();
        }
    }

    // ---- Phase E: build candidate SoA (overlay on sc) ----
    float* cy0  = sc;
    float* cx0  = sc + 256;
    float* cy1  = sc + 512;
    float* cx1  = sc + 768;
    float* cscv = sc + 1024;
    float* cclv = sc + 1280;
    {
        unsigned long long key = keys[t];
        int idx = 8191 - (int)(key & 0x1FFFull);
        float s = __uint_as_float((unsigned)(key >> 13));
        float y0 = 0.f, x0 = 0.f, y1 = 0.f, x1 = 0.f, cl = 0.f;
        if (idx < NITEM) {
            int cell = idx >> 1;
            int bb = idx & 1;
            int ci = cell / SDIM;
            int cj = cell - ci * SDIM;
            float4 cd = *(const float4*)(coord + ((long)cell * 2 + bb) * 4);
            float x = __fdiv_rn(cd.x + (float)cj, 56.0f);
            float y = __fdiv_rn(cd.y + (float)ci, 56.0f);
            float wh = (cd.z * cd.z) * 0.5f;
            float hh = (cd.w * cd.w) * 0.5f;
            y0 = y - hh; x0 = x - wh; y1 = y + hh; x1 = x + wh;
            cl = (float)gc[idx];
        } else {
            s = 0.0f;
        }
        cy0[t] = y0; cx0[t] = x0; cy1[t] = y1; cx1[t] = x1; cscv[t] = s; cclv[t] = cl;
    }
    __syncthreads();

    // ---- Phase F: warp-only greedy NMS (warp 0, candidates in registers) ----
    if (warp == 0) {
        float by0[8], bx0[8], by1[8], bx1[8], bar[8];
        #pragma unroll
        for (int k = 0; k < 8; ++k) {
            int c = lane * 8 + k;
            by0[k] = cy0[c]; bx0[k] = cx0[c]; by1[k] = cy1[c]; bx1[k] = cx1[c];
            bar[k] = __fmul_rn(fmaxf(by1[k] - by0[k], 0.0f), fmaxf(bx1[k] - bx0[k], 0.0f));
        }
        unsigned mask = 0xFFu;  // validity of my 8 candidates

        for (int r = 0; r < MAXOUT; ++r) {
            unsigned act = __ballot_sync(0xFFFFFFFFu, mask != 0u);
            int p = -1;
            if (act) {
                int lf = __ffs(act) - 1;                       // first lane with a valid cand
                unsigned mlf = __shfl_sync(0xFFFFFFFFu, mask, lf);
                p = lf * 8 + (__ffs(mlf) - 1);                 // first valid overall (sorted)
            }
            if (lane == 0) picks[r] = p;
            if (p >= 0) {
                float py0 = cy0[p], px0 = cx0[p], py1 = cy1[p], px1 = cx1[p];
                float parea = __fmul_rn(fmaxf(py1 - py0, 0.0f), fmaxf(px1 - px0, 0.0f));
                #pragma unroll
                for (int k = 0; k < 8; ++k) {
                    if ((mask >> k) & 1u) {
                        float iy = fmaxf(0.0f, fminf(py1, by1[k]) - fmaxf(py0, by0[k]));
                        float ix = fmaxf(0.0f, fminf(px1, bx1[k]) - fmaxf(px0, bx0[k]));
                        float inter = __fmul_rn(iy, ix);
                        float uni = parea + bar[k] - inter;
                        float iou = (uni > 0.0f) ? __fdiv_rn(inter, uni) : 0.0f;
                        if (iou > 0.4f) mask &= ~(1u << k);
                    }
                }
                if (lane == (p >> 3)) mask &= ~(1u << (p & 7));
            }
        }
    }
    __syncthreads();

    // ---- parallel output write: 30 rows x 6 comps ----
    if (t < MAXOUT * 6) {
        int r = t / 6, c = t - r * 6;
        int p = picks[r];
        float v = 0.0f;
        if (p >= 0) v = sc[c * 256 + p];   // SoA is contiguous: [y0,x0,y1,x1,score,class]
        out[(long)img * (MAXOUT * 6) + t] = v;
    }
}

extern "C" void kernel_launch(void* const* d_in, const int* in_sizes, int n_in,
                              void* d_out, int out_size)
{
    const float* in = (const float*)d_in[0];
    float* out = (float*)d_out;
    decode_kernel<<<(BATCH * NCELL + 255) / 256, 256>>>(in);
    nms_kernel<<<BATCH, 256>>>(in, out);
}

// round 4
// speedup vs baseline: 1.7883x; 1.7883x over previous
#include <cuda_runtime.h>

#define SDIM 56
#define NCELL 3136
#define NITEM 6272
#define NCLS 20
#define IMG_STRIDE 94080
#define CONF_OFF 62720
#define COORD_OFF 68992
#define MAXOUT 30
#define NCAND 256
#define KEYBUF 2048
#define BATCH 256
#define NT 512

__device__ float g_scores[BATCH * NITEM];
__device__ unsigned char g_cls[BATCH * NITEM];

// ---------------------------------------------------------------------------
// Kernel 1: decode scores + argmax class for every (cell, box). One thread/cell.
// ---------------------------------------------------------------------------
__global__ __launch_bounds__(256) void decode_kernel(const float* __restrict__ in)
{
    int gcell = blockIdx.x * 256 + threadIdx.x;
    if (gcell >= BATCH * NCELL) return;
    int img  = gcell / NCELL;
    int cell = gcell - img * NCELL;

    const float* base = in + (long)img * IMG_STRIDE;
    const float4* cp = (const float4*)(base + cell * NCLS);
    float p[NCLS];
    #pragma unroll
    for (int k = 0; k < 5; ++k) {
        float4 v = cp[k];
        p[4*k+0] = v.x; p[4*k+1] = v.y; p[4*k+2] = v.z; p[4*k+3] = v.w;
    }
    const float2 cf = *(const float2*)(base + CONF_OFF + cell * 2);
    float b0 = -1.0f, b1 = -1.0f;
    int a0 = 0, a1 = 0;
    #pragma unroll
    for (int c = 0; c < NCLS; ++c) {
        float v0 = cf.x * p[c];
        float v1 = cf.y * p[c];
        if (v0 > b0) { b0 = v0; a0 = c; }
        if (v1 > b1) { b1 = v1; a1 = c; }
    }
    float s0 = (b0 >= 0.1f) ? b0 : 0.0f;
    float s1 = (b1 >= 0.1f) ? b1 : 0.0f;
    long o = (long)img * NITEM + cell * 2;
    *(float2*)(g_scores + o) = make_float2(s0, s1);
    g_cls[o + 0] = (unsigned char)a0;
    g_cls[o + 1] = (unsigned char)a1;
}

// ---------------------------------------------------------------------------
// Kernel 2: per-image top-256 selection + greedy NMS. One block (512t) per image.
// ---------------------------------------------------------------------------
__global__ __launch_bounds__(NT, 2) void nms_kernel(const float* __restrict__ in,
                                                    float* __restrict__ out)
{
    __shared__ float sc[NITEM];                               // scores; SoA overlay later
    __shared__ __align__(16) unsigned long long keys[KEYBUF]; // overlays 1024-bin histogram
    __shared__ int wsum[16];
    __shared__ int picks[MAXOUT];
    __shared__ unsigned int wvalid[2][8];
    __shared__ int s_binsel;
    __shared__ int s_cnt;

    const int img = blockIdx.x;
    const int t = threadIdx.x;
    const int lane = t & 31;
    const int warp = t >> 5;
    const float* coord = in + (long)img * IMG_STRIDE + COORD_OFF;
    const float* gs = g_scores + (long)img * NITEM;
    const unsigned char* gc = g_cls + (long)img * NITEM;

    // ---- Phase A: load scores ----
    for (int i = t; i < NITEM / 4; i += NT)
        ((float4*)sc)[i] = ((const float4*)gs)[i];

    // ---- Phase B: 1024-bin histogram ----
    int* hist = (int*)keys;
    for (int k = t; k < 1024; k += NT) hist[k] = 0;
    if (t == 0) { s_binsel = 0; s_cnt = 0; }
    __syncthreads();
    for (int i = t; i < NITEM; i += NT) {
        int b = (int)(sc[i] * 1024.0f);
        b = b < 0 ? 0 : (b > 1023 ? 1023 : b);
        atomicAdd(&hist[b], 1);
    }
    __syncthreads();

    // ---- parallel suffix scan: largest bin b with suffix-count >= 256 ----
    {
        int2 h = ((const int2*)hist)[t];                 // bins 2t, 2t+1
        int v = h.x + h.y;
        #pragma unroll
        for (int off = 1; off < 32; off <<= 1) {
            int o = __shfl_down_sync(0xFFFFFFFFu, v, off);
            if (lane + off < 32) v += o;
        }
        if (lane == 0) wsum[warp] = v;
        __syncthreads();
        int tail = 0;
        #pragma unroll
        for (int w2 = 0; w2 < 16; ++w2) if (w2 > warp) tail += wsum[w2];
        int sfx0 = v + tail;            // suffix count at bin 2t
        int sfx1 = sfx0 - h.x;          // suffix count at bin 2t+1
        int best = -1;
        if      (sfx1 >= NCAND) best = 2*t + 1;
        else if (sfx0 >= NCAND) best = 2*t;
        if (best > 0) atomicMax(&s_binsel, best);
    }
    __syncthreads();
    const int bstar = s_binsel;

    // ---- Phase C: gather survivor keys ----
    // key = score_bits(31b) << 13 | (8191 - idx): desc key order == lax.top_k order
    for (int i = t; i < NITEM; i += NT) {
        float s = sc[i];
        int b = (int)(s * 1024.0f);
        b = b < 0 ? 0 : (b > 1023 ? 1023 : b);
        if (b >= bstar) {
            int pos = atomicAdd(&s_cnt, 1);
            if (pos < KEYBUF) {
                unsigned long long key =
                    ((unsigned long long)__float_as_uint(s) << 13) |
                    (unsigned long long)(8191 - i);
                keys[pos] = key;
            }
        }
    }
    __syncthreads();
    int n = s_cnt; if (n > KEYBUF) n = KEYBUF;
    int np = NT; while (np < n) np <<= 1;
    for (int i = n + t; i < np; i += NT) keys[i] = 0ull;
    __syncthreads();

    // ---- Phase D: bitonic sort descending ----
    unsigned long long a = keys[t];
    if (np == NT) {
        // register sort: 1 key/thread; shfl for j<32, smem for j>=32
        #pragma unroll
        for (int k = 2; k <= NT; k <<= 1) {
            #pragma unroll
            for (int j = k >> 1; j > 0; j >>= 1) {
                bool up = ((t & k) == 0);
                unsigned long long b2;
                if (j >= 32) {
                    __syncthreads();
                    keys[t] = a;
                    __syncthreads();
                    b2 = keys[t ^ j];
                } else {
                    b2 = __shfl_xor_sync(0xFFFFFFFFu, a, j);
                }
                bool keep_max = (up == ((t & j) == 0));
                bool amax = (a > b2);
                a = (keep_max == amax) ? a : b2;
            }
        }
    } else {
        // fallback smem sort for np > 512
        for (int k = 2; k <= np; k <<= 1) {
            for (int j = k >> 1; j > 0; j >>= 1) {
                for (int i = t; i < np; i += NT) {
                    int ixj = i ^ j;
                    if (ixj > i) {
                        unsigned long long x = keys[i];
                        unsigned long long y = keys[ixj];
                        bool up = ((i & k) == 0);
                        bool doswap = up ? (x < y) : (x > y);
                        if (doswap) { keys[i] = y; keys[ixj] = x; }
                    }
                }
                __syncthreads();
            }
        }
        a = keys[t];
    }
    __syncthreads();

    // ---- Phase E: build candidate SoA (overlay on sc); init NMS validity ----
    float* cy0  = sc;
    float* cx0  = sc + 256;
    float* cy1  = sc + 512;
    float* cx1  = sc + 768;
    float* cscv = sc + 1024;
    float* cclv = sc + 1280;
    if (t < NCAND) {
        int idx = 8191 - (int)(a & 0x1FFFull);
        float s = __uint_as_float((unsigned)(a >> 13));
        float y0 = 0.f, x0 = 0.f, y1 = 0.f, x1 = 0.f, cl = 0.f;
        if (idx < NITEM) {
            int cell = idx >> 1;
            int bb = idx & 1;
            int ci = cell / SDIM;
            int cj = cell - ci * SDIM;
            float4 cd = *(const float4*)(coord + ((long)cell * 2 + bb) * 4);
            float x = __fdiv_rn(cd.x + (float)cj, 56.0f);
            float y = __fdiv_rn(cd.y + (float)ci, 56.0f);
            float wh = (cd.z * cd.z) * 0.5f;
            float hh = (cd.w * cd.w) * 0.5f;
            y0 = y - hh; x0 = x - wh; y1 = y + hh; x1 = x + wh;
            cl = (float)gc[idx];
        } else {
            s = 0.0f;
        }
        cy0[t] = y0; cx0[t] = x0; cy1[t] = y1; cx1[t] = x1; cscv[t] = s; cclv[t] = cl;
    }
    if (t < 8) wvalid[0][t] = 0xFFFFFFFFu;
    __syncthreads();

    // ---- Phase F: block-parallel greedy NMS, one sync/round, double-buffered ----
    const bool is_cand = (t < NCAND);
    const int ci2 = is_cand ? t : 0;
    const float my_y0 = cy0[ci2], my_x0 = cx0[ci2];
    const float my_y1 = cy1[ci2], my_x1 = cx1[ci2];
    const float my_area = __fmul_rn(fmaxf(my_y1 - my_y0, 0.0f), fmaxf(my_x1 - my_x0, 0.0f));

    for (int r = 0; r < MAXOUT; ++r) {
        const int cur = r & 1;
        // every thread redundantly finds the first valid candidate (sorted => argmax)
        int p = -1;
        #pragma unroll
        for (int w2 = 0; w2 < 8; ++w2) {
            unsigned mm = wvalid[cur][w2];
            if (p < 0 && mm) p = w2 * 32 + __ffs(mm) - 1;
        }
        if (t == 0) picks[r] = p;

        bool nv = is_cand && ((wvalid[cur][warp & 7] >> lane) & 1u);
        if (p >= 0 && is_cand) {                 // warp-uniform skip for warps 8..15
            float py0 = cy0[p], px0 = cx0[p], py1 = cy1[p], px1 = cx1[p];
            float parea = __fmul_rn(fmaxf(py1 - py0, 0.0f), fmaxf(px1 - px0, 0.0f));
            float iy = fmaxf(0.0f, fminf(py1, my_y1) - fmaxf(py0, my_y0));
            float ix = fmaxf(0.0f, fminf(px1, my_x1) - fmaxf(px0, my_x0));
            float inter = __fmul_rn(iy, ix);
            float uni = parea + my_area - inter;
            float iou = (uni > 0.0f) ? __fdiv_rn(inter, uni) : 0.0f;
            if (iou > 0.4f) nv = false;
            if (t == p) nv = false;
        }
        unsigned bal = __ballot_sync(0xFFFFFFFFu, nv);
        if (warp < 8 && lane == 0) wvalid[cur ^ 1][warp] = bal;
        __syncthreads();
    }

    // ---- parallel output write: 30 rows x 6 comps ----
    if (t < MAXOUT * 6) {
        int r = t / 6, c = t - r * 6;
        int p = picks[r];
        float v = 0.0f;
        if (p >= 0) v = sc[c * 256 + p];   // SoA contiguous: [y0,x0,y1,x1,score,class]
        out[(long)img * (MAXOUT * 6) + t] = v;
    }
}

extern "C" void kernel_launch(void* const* d_in, const int* in_sizes, int n_in,
                              void* d_out, int out_size)
{
    const float* in = (const float*)d_in[0];
    float* out = (float*)d_out;
    decode_kernel<<<(BATCH * NCELL + 255) / 256, 256>>>(in);
    nms_kernel<<<BATCH, NT>>>(in, out);
}